// round 12
// baseline (speedup 1.0000x reference)
#include <cuda_runtime.h>

#define N_NODES 100000
#define N_EDGES 1600000
#define D_IN    256
#define D_HID   64
#define D_OUT   32
#define NUM_PROP 10
#define ALPHA   0.1f

#define SCAN_B   1024
#define NPART    ((N_NODES + SCAN_B - 1) / SCAN_B)   // 98

#define CSR_BLOCKS  64
#define CSR_THREADS 256
#define CSR_TOTAL   (CSR_BLOCKS * CSR_THREADS)

typedef unsigned long long u64;

// ---------------- device scratch (no allocations allowed) ----------------
__device__ int   g_cnt[N_NODES];
__device__ int   g_rowptr[N_NODES + 1];
__device__ int   g_part[NPART];
__device__ int   g_partpref[NPART];
__device__ __align__(256) int2  g_edges[N_EDGES];
__device__ __align__(256) float g_x0[(size_t)N_NODES * D_OUT];
__device__ __align__(256) float g_bufA[(size_t)N_NODES * D_OUT];
__device__ __align__(256) float g_bufB[(size_t)N_NODES * D_OUT];

// manual grid barrier state (generation-based; survives graph replays)
__device__ int g_bar_cnt = 0;
__device__ int g_bar_gen = 0;

// ---------------- packed fp32x2 helpers (sm_103a) ----------------
__device__ __forceinline__ u64 fma2(u64 a, u64 b, u64 c) {
    u64 d;
    asm("fma.rn.f32x2 %0, %1, %2, %3;" : "=l"(d) : "l"(a), "l"(b), "l"(c));
    return d;
}
__device__ __forceinline__ u64 pack2(float x) {
    u64 d;
    asm("mov.b64 %0, {%1, %1};" : "=l"(d) : "f"(x));
    return d;
}
__device__ __forceinline__ float2 unpack2(u64 p) {
    float2 r;
    asm("mov.b64 {%0, %1}, %2;" : "=f"(r.x), "=f"(r.y) : "l"(p));
    return r;
}

// ---------------- fused MLP: x0 = relu(F @ W1 + b1) @ W2 + b2 ----------------
__global__ __launch_bounds__(128) void k_mlp(const float* __restrict__ F,
                                             const float* __restrict__ W1,
                                             const float* __restrict__ b1,
                                             const float* __restrict__ W2,
                                             const float* __restrict__ b2) {
    extern __shared__ float smem[];
    float* sW1 = smem;                 // [256][64]
    float* sW2 = smem + D_IN * D_HID;  // [64][32]

    {
        const float4* src1 = (const float4*)W1;
        float4* dst1 = (float4*)sW1;
        for (int i = threadIdx.x; i < D_IN * D_HID / 4; i += 128) dst1[i] = src1[i];
        const float4* src2 = (const float4*)W2;
        float4* dst2 = (float4*)sW2;
        for (int i = threadIdx.x; i < D_HID * D_OUT / 4; i += 128) dst2[i] = src2[i];
    }
    __syncthreads();

    int node = blockIdx.x * 128 + threadIdx.x;
    if (node >= N_NODES) return;

    u64 acc[D_HID / 2];
    {
        const u64* b1p = (const u64*)b1;
#pragma unroll
        for (int p = 0; p < D_HID / 2; p++) acc[p] = __ldg(&b1p[p]);
    }

    const float4* Fr = (const float4*)(F + (size_t)node * D_IN);
    for (int k4 = 0; k4 < D_IN / 4; k4++) {
        float4 f = __ldg(&Fr[k4]);
        float fv[4] = {f.x, f.y, f.z, f.w};
#pragma unroll
        for (int s = 0; s < 4; s++) {
            int k = k4 * 4 + s;
            u64 fp = pack2(fv[s]);
            const u64* wrow = (const u64*)(sW1 + k * D_HID);
#pragma unroll
            for (int p = 0; p < D_HID / 2; p++)
                acc[p] = fma2(fp, wrow[p], acc[p]);
        }
    }

    u64 o[D_OUT / 2];
    {
        const u64* b2p = (const u64*)b2;
#pragma unroll
        for (int q = 0; q < D_OUT / 2; q++) o[q] = __ldg(&b2p[q]);
    }

#pragma unroll
    for (int p = 0; p < D_HID / 2; p++) {
        float2 h = unpack2(acc[p]);
        u64 hap = pack2(fmaxf(h.x, 0.f));
        u64 hbp = pack2(fmaxf(h.y, 0.f));
        const u64* w2a = (const u64*)(sW2 + (2 * p)     * D_OUT);
        const u64* w2b = (const u64*)(sW2 + (2 * p + 1) * D_OUT);
#pragma unroll
        for (int q = 0; q < D_OUT / 2; q++) {
            o[q] = fma2(hap, w2a[q], o[q]);
            o[q] = fma2(hbp, w2b[q], o[q]);
        }
    }

    ulonglong2* X = (ulonglong2*)(g_x0 + (size_t)node * D_OUT);
#pragma unroll
    for (int q2 = 0; q2 < D_OUT / 4; q2++)
        X[q2] = make_ulonglong2(o[2 * q2], o[2 * q2 + 1]);
}

// ---------------- fused CSR build (single kernel, manual grid barrier) ----------------
__device__ __forceinline__ void grid_sync_() {
    __syncthreads();
    if (threadIdx.x == 0) {
        int gen = *((volatile int*)&g_bar_gen);   // read BEFORE arriving
        __threadfence();
        if (atomicAdd(&g_bar_cnt, 1) == CSR_BLOCKS - 1) {
            g_bar_cnt = 0;
            __threadfence();
            atomicExch(&g_bar_gen, gen + 1);
        } else {
            while (*((volatile int*)&g_bar_gen) == gen) { }
        }
        __threadfence();
    }
    __syncthreads();
}

__global__ __launch_bounds__(CSR_THREADS) void k_csr(const int* __restrict__ row,
                                                     const int* __restrict__ col,
                                                     const float* __restrict__ val) {
    int tid = blockIdx.x * CSR_THREADS + threadIdx.x;
    int lane = threadIdx.x & 31, wid = threadIdx.x >> 5;
    __shared__ int sred[CSR_THREADS / 32];

    // 1. zero counts
    for (int i = tid; i < N_NODES; i += CSR_TOTAL) g_cnt[i] = 0;
    grid_sync_();

    // 2. histogram
    for (int e = tid; e < N_EDGES; e += CSR_TOTAL) atomicAdd(&g_cnt[row[e]], 1);
    grid_sync_();

    // 3. per-segment sums (segment = 1024 nodes)
    for (int seg = blockIdx.x; seg < NPART; seg += CSR_BLOCKS) {
        int base = seg * SCAN_B;
        int s = 0;
        for (int i = threadIdx.x; i < SCAN_B; i += CSR_THREADS) {
            int idx = base + i;
            s += (idx < N_NODES) ? g_cnt[idx] : 0;
        }
#pragma unroll
        for (int off = 16; off > 0; off >>= 1) s += __shfl_down_sync(0xffffffffu, s, off);
        if (lane == 0) sred[wid] = s;
        __syncthreads();
        if (wid == 0) {
            int w = (lane < CSR_THREADS / 32) ? sred[lane] : 0;
#pragma unroll
            for (int off = 4; off > 0; off >>= 1) w += __shfl_down_sync(0xffffffffu, w, off);
            if (lane == 0) g_part[seg] = w;
        }
        __syncthreads();
    }
    grid_sync_();

    // 4. scan the 98 partials (block 0; serial over smem is ~3k cyc)
    if (blockIdx.x == 0) {
        __shared__ int sp[NPART];
        if (threadIdx.x < NPART) sp[threadIdx.x] = g_part[threadIdx.x];
        __syncthreads();
        if (threadIdx.x == 0) {
            int run = 0;
            for (int b = 0; b < NPART; b++) { int v = sp[b]; sp[b] = run; run += v; }
            g_rowptr[N_NODES] = run;   // == N_EDGES
        }
        __syncthreads();
        if (threadIdx.x < NPART) g_partpref[threadIdx.x] = sp[threadIdx.x];
    }
    grid_sync_();

    // 5. final scan per segment: 4 consecutive elements per thread
    __shared__ int swarp[CSR_THREADS / 32];
    for (int seg = blockIdx.x; seg < NPART; seg += CSR_BLOCKS) {
        int base = seg * SCAN_B;
        int i0 = base + threadIdx.x * 4;
        int4 v = make_int4(0, 0, 0, 0);
        if (i0 + 3 < N_NODES) {
            v = *(const int4*)&g_cnt[i0];
        } else {
            if (i0     < N_NODES) v.x = g_cnt[i0];
            if (i0 + 1 < N_NODES) v.y = g_cnt[i0 + 1];
            if (i0 + 2 < N_NODES) v.z = g_cnt[i0 + 2];
            if (i0 + 3 < N_NODES) v.w = g_cnt[i0 + 3];
        }
        int t = v.x + v.y + v.z + v.w;
        int incl = t;
#pragma unroll
        for (int off = 1; off < 32; off <<= 1) {
            int u = __shfl_up_sync(0xffffffffu, incl, off);
            if (lane >= off) incl += u;
        }
        if (lane == 31) swarp[wid] = incl;
        __syncthreads();
        if (wid == 0) {
            int w = (lane < CSR_THREADS / 32) ? swarp[lane] : 0;
#pragma unroll
            for (int off = 1; off < CSR_THREADS / 32; off <<= 1) {
                int u = __shfl_up_sync(0xffffffffu, w, off);
                if (lane >= off) w += u;
            }
            if (lane < CSR_THREADS / 32) swarp[lane] = w;
        }
        __syncthreads();
        int texcl = incl - t + (wid ? swarp[wid - 1] : 0) + g_partpref[seg];
        int e0 = texcl;
        int e1 = e0 + v.x, e2 = e1 + v.y, e3 = e2 + v.z;
        if (i0     < N_NODES) { g_rowptr[i0]     = e0; g_cnt[i0]     = e0; }
        if (i0 + 1 < N_NODES) { g_rowptr[i0 + 1] = e1; g_cnt[i0 + 1] = e1; }
        if (i0 + 2 < N_NODES) { g_rowptr[i0 + 2] = e2; g_cnt[i0 + 2] = e2; }
        if (i0 + 3 < N_NODES) { g_rowptr[i0 + 3] = e3; g_cnt[i0 + 3] = e3; }
        __syncthreads();
    }
    grid_sync_();

    // 6. scatter (counting-sort by row)
    for (int e = tid; e < N_EDGES; e += CSR_TOTAL) {
        int r = row[e];
        int p = atomicAdd(&g_cnt[r], 1);
        g_edges[p] = make_int2(col[e], __float_as_int(val[e]));
    }
}

// ---------------- propagation: warp-per-row, lane = dim, 16 gathers in flight ----------------
__global__ __launch_bounds__(256) void k_prop(int it, float* __restrict__ dout) {
    const float* __restrict__ xin =
        (it == 0) ? g_x0 : ((it & 1) ? g_bufA : g_bufB);
    float* __restrict__ xout =
        (it == NUM_PROP - 1) ? dout : ((it & 1) ? g_bufB : g_bufA);

    int warp = (blockIdx.x * blockDim.x + threadIdx.x) >> 5;
    int lane = threadIdx.x & 31;
    if (warp >= N_NODES) return;

    int start = __ldg(&g_rowptr[warp]);
    int end   = __ldg(&g_rowptr[warp + 1]);

    const float* __restrict__ xl = xin + lane;

    float acc = 0.f;
    int e = start;

    if ((e & 1) && e < end) {
        int2 c = __ldg(&g_edges[e]);
        acc += __int_as_float(c.y) * __ldg(&xl[(size_t)c.x * D_OUT]);
        e++;
    }
    for (; e + 15 < end; e += 16) {
        int4 p[8];
#pragma unroll
        for (int j = 0; j < 8; j++) p[j] = __ldg((const int4*)&g_edges[e + 2 * j]);
        float v[16];
#pragma unroll
        for (int j = 0; j < 8; j++) {
            v[2*j]   = __ldg(&xl[(size_t)p[j].x * D_OUT]);
            v[2*j+1] = __ldg(&xl[(size_t)p[j].z * D_OUT]);
        }
#pragma unroll
        for (int j = 0; j < 8; j++) {
            acc += __int_as_float(p[j].y) * v[2*j];
            acc += __int_as_float(p[j].w) * v[2*j+1];
        }
    }
    for (; e + 3 < end; e += 4) {
        int4 p0 = __ldg((const int4*)&g_edges[e]);
        int4 p1 = __ldg((const int4*)&g_edges[e + 2]);
        float v0 = __ldg(&xl[(size_t)p0.x * D_OUT]);
        float v1 = __ldg(&xl[(size_t)p0.z * D_OUT]);
        float v2 = __ldg(&xl[(size_t)p1.x * D_OUT]);
        float v3 = __ldg(&xl[(size_t)p1.z * D_OUT]);
        acc += __int_as_float(p0.y) * v0;
        acc += __int_as_float(p0.w) * v1;
        acc += __int_as_float(p1.y) * v2;
        acc += __int_as_float(p1.w) * v3;
    }
    if (e + 1 < end) {
        int4 p0 = __ldg((const int4*)&g_edges[e]);
        acc += __int_as_float(p0.y) * __ldg(&xl[(size_t)p0.x * D_OUT]);
        acc += __int_as_float(p0.w) * __ldg(&xl[(size_t)p0.z * D_OUT]);
        e += 2;
    }
    if (e < end) {
        int2 c = __ldg(&g_edges[e]);
        acc += __int_as_float(c.y) * __ldg(&xl[(size_t)c.x * D_OUT]);
    }

    xout[(size_t)warp * D_OUT + lane] =
        (1.0f - ALPHA) * acc + ALPHA * __ldg(&g_x0[(size_t)warp * D_OUT + lane]);
}

// ---------------- launch ----------------
extern "C" void kernel_launch(void* const* d_in, const int* in_sizes, int n_in,
                              void* d_out, int out_size) {
    const float* F   = (const float*)d_in[0];
    const int*   row = (const int*)  d_in[1];
    const int*   col = (const int*)  d_in[2];
    const float* ev  = (const float*)d_in[3];
    const float* W1  = (const float*)d_in[4];
    const float* b1  = (const float*)d_in[5];
    const float* W2  = (const float*)d_in[6];
    const float* b2  = (const float*)d_in[7];
    float* out = (float*)d_out;

    const int MLP_SMEM = (D_IN * D_HID + D_HID * D_OUT) * sizeof(float);  // 72 KB
    cudaFuncSetAttribute(k_mlp, cudaFuncAttributeMaxDynamicSharedMemorySize, MLP_SMEM);

    // Fork: CSR build (1 fused kernel) on side stream, MLP on capture stream.
    cudaStream_t side;
    cudaEvent_t evFork, evJoin;
    cudaStreamCreateWithFlags(&side, cudaStreamNonBlocking);
    cudaEventCreateWithFlags(&evFork, cudaEventDisableTiming);
    cudaEventCreateWithFlags(&evJoin, cudaEventDisableTiming);

    cudaEventRecord(evFork, 0);
    cudaStreamWaitEvent(side, evFork, 0);

    k_mlp<<<(N_NODES + 127) / 128, 128, MLP_SMEM>>>(F, W1, b1, W2, b2);   // launch #1
    k_csr<<<CSR_BLOCKS, CSR_THREADS, 0, side>>>(row, col, ev);            // launch #2

    cudaEventRecord(evJoin, side);
    cudaStreamWaitEvent(0, evJoin, 0);

    cudaEventDestroy(evFork);
    cudaEventDestroy(evJoin);
    cudaStreamDestroy(side);

    // 10 propagation rounds; launches #3..#12 -> ncu (4th) lands on it=1
    int warps_per_block = 256 / 32;
    int grid = (N_NODES + warps_per_block - 1) / warps_per_block;
    for (int it = 0; it < NUM_PROP; it++)
        k_prop<<<grid, 256>>>(it, out);
}

// round 13
// speedup vs baseline: 1.9181x; 1.9181x over previous
#include <cuda_runtime.h>

#define N_NODES 100000
#define N_EDGES 1600000
#define D_IN    256
#define D_HID   64
#define D_OUT   32
#define NUM_PROP 10
#define ALPHA   0.1f

#define SCAN_B   1024
#define NPART    ((N_NODES + SCAN_B - 1) / SCAN_B)   // 98

#define ROWS_PER_WARP 4
#define PROP_THREADS  256
#define PROP_GRID     (N_NODES / (ROWS_PER_WARP * PROP_THREADS / 32))   // 3125

typedef unsigned long long u64;

// ---------------- device scratch (no allocations allowed) ----------------
__device__ int   g_cnt[N_NODES];
__device__ int   g_rowptr[N_NODES + 1];
__device__ int   g_part[NPART];
__device__ int   g_partpref[NPART];
__device__ __align__(256) int2  g_edges[N_EDGES];
__device__ __align__(256) float g_x0[(size_t)N_NODES * D_OUT];
__device__ __align__(256) float g_bufA[(size_t)N_NODES * D_OUT];
__device__ __align__(256) float g_bufB[(size_t)N_NODES * D_OUT];

// ---------------- packed fp32x2 helpers (sm_103a) ----------------
__device__ __forceinline__ u64 fma2(u64 a, u64 b, u64 c) {
    u64 d;
    asm("fma.rn.f32x2 %0, %1, %2, %3;" : "=l"(d) : "l"(a), "l"(b), "l"(c));
    return d;
}
__device__ __forceinline__ u64 pack2(float x) {
    u64 d;
    asm("mov.b64 %0, {%1, %1};" : "=l"(d) : "f"(x));
    return d;
}
__device__ __forceinline__ float2 unpack2(u64 p) {
    float2 r;
    asm("mov.b64 {%0, %1}, %2;" : "=f"(r.x), "=f"(r.y) : "l"(p));
    return r;
}

// ---------------- fused MLP: x0 = relu(F @ W1 + b1) @ W2 + b2 ----------------
__global__ __launch_bounds__(128) void k_mlp(const float* __restrict__ F,
                                             const float* __restrict__ W1,
                                             const float* __restrict__ b1,
                                             const float* __restrict__ W2,
                                             const float* __restrict__ b2) {
    extern __shared__ float smem[];
    float* sW1 = smem;                 // [256][64]
    float* sW2 = smem + D_IN * D_HID;  // [64][32]

    {
        const float4* src1 = (const float4*)W1;
        float4* dst1 = (float4*)sW1;
        for (int i = threadIdx.x; i < D_IN * D_HID / 4; i += 128) dst1[i] = src1[i];
        const float4* src2 = (const float4*)W2;
        float4* dst2 = (float4*)sW2;
        for (int i = threadIdx.x; i < D_HID * D_OUT / 4; i += 128) dst2[i] = src2[i];
    }
    __syncthreads();

    int node = blockIdx.x * 128 + threadIdx.x;
    if (node >= N_NODES) return;

    u64 acc[D_HID / 2];
    {
        const u64* b1p = (const u64*)b1;
#pragma unroll
        for (int p = 0; p < D_HID / 2; p++) acc[p] = __ldg(&b1p[p]);
    }

    const float4* Fr = (const float4*)(F + (size_t)node * D_IN);
    for (int k4 = 0; k4 < D_IN / 4; k4++) {
        float4 f = __ldg(&Fr[k4]);
        float fv[4] = {f.x, f.y, f.z, f.w};
#pragma unroll
        for (int s = 0; s < 4; s++) {
            int k = k4 * 4 + s;
            u64 fp = pack2(fv[s]);
            const u64* wrow = (const u64*)(sW1 + k * D_HID);
#pragma unroll
            for (int p = 0; p < D_HID / 2; p++)
                acc[p] = fma2(fp, wrow[p], acc[p]);
        }
    }

    u64 o[D_OUT / 2];
    {
        const u64* b2p = (const u64*)b2;
#pragma unroll
        for (int q = 0; q < D_OUT / 2; q++) o[q] = __ldg(&b2p[q]);
    }

#pragma unroll
    for (int p = 0; p < D_HID / 2; p++) {
        float2 h = unpack2(acc[p]);
        u64 hap = pack2(fmaxf(h.x, 0.f));
        u64 hbp = pack2(fmaxf(h.y, 0.f));
        const u64* w2a = (const u64*)(sW2 + (2 * p)     * D_OUT);
        const u64* w2b = (const u64*)(sW2 + (2 * p + 1) * D_OUT);
#pragma unroll
        for (int q = 0; q < D_OUT / 2; q++) {
            o[q] = fma2(hap, w2a[q], o[q]);
            o[q] = fma2(hbp, w2b[q], o[q]);
        }
    }

    ulonglong2* X = (ulonglong2*)(g_x0 + (size_t)node * D_OUT);
#pragma unroll
    for (int q2 = 0; q2 < D_OUT / 4; q2++)
        X[q2] = make_ulonglong2(o[2 * q2], o[2 * q2 + 1]);
}

// ---------------- CSR build (multi-kernel, wide grids) ----------------
__global__ void k_zero_cnt() {
    int i = blockIdx.x * blockDim.x + threadIdx.x;
    if (i < N_NODES) g_cnt[i] = 0;
}

__global__ void k_hist(const int* __restrict__ row) {
    int e = blockIdx.x * blockDim.x + threadIdx.x;
    if (e < N_EDGES) atomicAdd(&g_cnt[row[e]], 1);
}

__global__ __launch_bounds__(SCAN_B) void k_blocksum() {
    int i = blockIdx.x * SCAN_B + threadIdx.x;
    int v = (i < N_NODES) ? g_cnt[i] : 0;
#pragma unroll
    for (int off = 16; off > 0; off >>= 1)
        v += __shfl_down_sync(0xffffffffu, v, off);
    __shared__ int ws[SCAN_B / 32];
    if ((threadIdx.x & 31) == 0) ws[threadIdx.x >> 5] = v;
    __syncthreads();
    if (threadIdx.x < SCAN_B / 32) {
        int w = ws[threadIdx.x];
#pragma unroll
        for (int off = 16; off > 0; off >>= 1)
            w += __shfl_down_sync(0xffffffffu, w, off);
        if (threadIdx.x == 0) g_part[blockIdx.x] = w;
    }
}

__global__ __launch_bounds__(128) void k_scanpart() {
    __shared__ int s[NPART];
    int tid = threadIdx.x;
    if (tid < NPART) s[tid] = g_part[tid];
    __syncthreads();
    if (tid == 0) {
        int run = 0;
        for (int b = 0; b < NPART; b++) { int v = s[b]; s[b] = run; run += v; }
        g_rowptr[N_NODES] = run;
    }
    __syncthreads();
    if (tid < NPART) g_partpref[tid] = s[tid];
}

__global__ __launch_bounds__(SCAN_B) void k_scanfinal() {
    int i    = blockIdx.x * SCAN_B + threadIdx.x;
    int val  = (i < N_NODES) ? g_cnt[i] : 0;
    int lane = threadIdx.x & 31, wid = threadIdx.x >> 5;

    int v = val;
#pragma unroll
    for (int off = 1; off < 32; off <<= 1) {
        int t = __shfl_up_sync(0xffffffffu, v, off);
        if (lane >= off) v += t;
    }
    __shared__ int ws[SCAN_B / 32];
    if (lane == 31) ws[wid] = v;
    __syncthreads();
    if (wid == 0) {
        int w = (lane < SCAN_B / 32) ? ws[lane] : 0;
#pragma unroll
        for (int off = 1; off < 32; off <<= 1) {
            int t = __shfl_up_sync(0xffffffffu, w, off);
            if (lane >= off) w += t;
        }
        if (lane < SCAN_B / 32) ws[lane] = w;
    }
    __syncthreads();

    int excl = v - val + (wid ? ws[wid - 1] : 0) + g_partpref[blockIdx.x];
    if (i < N_NODES) {
        g_rowptr[i] = excl;
        g_cnt[i]    = excl;
    }
}

__global__ void k_scatter(const int* __restrict__ row,
                          const int* __restrict__ col,
                          const float* __restrict__ val) {
    int e = blockIdx.x * blockDim.x + threadIdx.x;
    if (e < N_EDGES) {
        int r = row[e];
        int p = atomicAdd(&g_cnt[r], 1);
        g_edges[p] = make_int2(col[e], __float_as_int(val[e]));
    }
}

// ---------------- propagation: 4 contiguous rows per warp ----------------
// rowptr for all 4 rows preloaded via one lane-parallel LDG + shfl, so each
// row's edge loads depend only on registers; successive rows' memory chains
// overlap. Blocks live 4x longer -> less launch/ramp churn.
__global__ __launch_bounds__(PROP_THREADS) void k_prop(int it, float* __restrict__ dout) {
    const float* __restrict__ xin =
        (it == 0) ? g_x0 : ((it & 1) ? g_bufA : g_bufB);
    float* __restrict__ xout =
        (it == NUM_PROP - 1) ? dout : ((it & 1) ? g_bufB : g_bufA);

    int warp = (blockIdx.x * PROP_THREADS + threadIdx.x) >> 5;
    int lane = threadIdx.x & 31;
    int base = warp * ROWS_PER_WARP;              // N_NODES % 4 == 0
    if (base >= N_NODES) return;

    // preload rowptr[base .. base+4] (5 values) in one LDG
    int rp = 0;
    if (lane <= ROWS_PER_WARP) rp = __ldg(&g_rowptr[base + lane]);

    const float* __restrict__ xl = xin + lane;

#pragma unroll
    for (int r = 0; r < ROWS_PER_WARP; r++) {
        int e   = __shfl_sync(0xffffffffu, rp, r);
        int end = __shfl_sync(0xffffffffu, rp, r + 1);
        int row = base + r;

        float acc = 0.f;

        if ((e & 1) && e < end) {
            int2 c = __ldg(&g_edges[e]);
            acc += __int_as_float(c.y) * __ldg(&xl[(size_t)c.x * D_OUT]);
            e++;
        }
        // 8 edges (4x LDG.128) per stage
        for (; e + 7 < end; e += 8) {
            int4 p0 = __ldg((const int4*)&g_edges[e]);
            int4 p1 = __ldg((const int4*)&g_edges[e + 2]);
            int4 p2 = __ldg((const int4*)&g_edges[e + 4]);
            int4 p3 = __ldg((const int4*)&g_edges[e + 6]);
            float v0 = __ldg(&xl[(size_t)p0.x * D_OUT]);
            float v1 = __ldg(&xl[(size_t)p0.z * D_OUT]);
            float v2 = __ldg(&xl[(size_t)p1.x * D_OUT]);
            float v3 = __ldg(&xl[(size_t)p1.z * D_OUT]);
            float v4 = __ldg(&xl[(size_t)p2.x * D_OUT]);
            float v5 = __ldg(&xl[(size_t)p2.z * D_OUT]);
            float v6 = __ldg(&xl[(size_t)p3.x * D_OUT]);
            float v7 = __ldg(&xl[(size_t)p3.z * D_OUT]);
            acc += __int_as_float(p0.y) * v0;
            acc += __int_as_float(p0.w) * v1;
            acc += __int_as_float(p1.y) * v2;
            acc += __int_as_float(p1.w) * v3;
            acc += __int_as_float(p2.y) * v4;
            acc += __int_as_float(p2.w) * v5;
            acc += __int_as_float(p3.y) * v6;
            acc += __int_as_float(p3.w) * v7;
        }
        if (e + 3 < end) {
            int4 p0 = __ldg((const int4*)&g_edges[e]);
            int4 p1 = __ldg((const int4*)&g_edges[e + 2]);
            acc += __int_as_float(p0.y) * __ldg(&xl[(size_t)p0.x * D_OUT]);
            acc += __int_as_float(p0.w) * __ldg(&xl[(size_t)p0.z * D_OUT]);
            acc += __int_as_float(p1.y) * __ldg(&xl[(size_t)p1.x * D_OUT]);
            acc += __int_as_float(p1.w) * __ldg(&xl[(size_t)p1.z * D_OUT]);
            e += 4;
        }
        if (e + 1 < end) {
            int4 p0 = __ldg((const int4*)&g_edges[e]);
            acc += __int_as_float(p0.y) * __ldg(&xl[(size_t)p0.x * D_OUT]);
            acc += __int_as_float(p0.w) * __ldg(&xl[(size_t)p0.z * D_OUT]);
            e += 2;
        }
        if (e < end) {
            int2 c = __ldg(&g_edges[e]);
            acc += __int_as_float(c.y) * __ldg(&xl[(size_t)c.x * D_OUT]);
        }

        xout[(size_t)row * D_OUT + lane] =
            (1.0f - ALPHA) * acc + ALPHA * __ldg(&g_x0[(size_t)row * D_OUT + lane]);
    }
}

// ---------------- launch ----------------
extern "C" void kernel_launch(void* const* d_in, const int* in_sizes, int n_in,
                              void* d_out, int out_size) {
    const float* F   = (const float*)d_in[0];
    const int*   row = (const int*)  d_in[1];
    const int*   col = (const int*)  d_in[2];
    const float* ev  = (const float*)d_in[3];
    const float* W1  = (const float*)d_in[4];
    const float* b1  = (const float*)d_in[5];
    const float* W2  = (const float*)d_in[6];
    const float* b2  = (const float*)d_in[7];
    float* out = (float*)d_out;

    const int MLP_SMEM = (D_IN * D_HID + D_HID * D_OUT) * sizeof(float);  // 72 KB
    cudaFuncSetAttribute(k_mlp, cudaFuncAttributeMaxDynamicSharedMemorySize, MLP_SMEM);

    // Fork: CSR build on a side stream, MLP on the main (capture) stream.
    cudaStream_t side;
    cudaEvent_t evFork, evJoin;
    cudaStreamCreateWithFlags(&side, cudaStreamNonBlocking);
    cudaEventCreateWithFlags(&evFork, cudaEventDisableTiming);
    cudaEventCreateWithFlags(&evJoin, cudaEventDisableTiming);

    cudaEventRecord(evFork, 0);
    cudaStreamWaitEvent(side, evFork, 0);

    // main stream: fused MLP head (FMA-bound)
    k_mlp<<<(N_NODES + 127) / 128, 128, MLP_SMEM>>>(F, W1, b1, W2, b2);

    // side stream: CSR build (memory/atomic-bound, wide grids)
    k_zero_cnt <<<(N_NODES + 255) / 256, 256, 0, side>>>();
    k_hist     <<<(N_EDGES + 255) / 256, 256, 0, side>>>(row);
    k_blocksum <<<NPART, SCAN_B, 0, side>>>();
    k_scanpart <<<1, 128, 0, side>>>();
    k_scanfinal<<<NPART, SCAN_B, 0, side>>>();
    k_scatter  <<<(N_EDGES + 255) / 256, 256, 0, side>>>(row, col, ev);

    cudaEventRecord(evJoin, side);
    cudaStreamWaitEvent(0, evJoin, 0);

    cudaEventDestroy(evFork);
    cudaEventDestroy(evJoin);
    cudaStreamDestroy(side);

    // 10 propagation rounds; last writes d_out directly
    for (int it = 0; it < NUM_PROP; it++)
        k_prop<<<PROP_GRID, PROP_THREADS>>>(it, out);
}